// round 8
// baseline (speedup 1.0000x reference)
#include <cuda_runtime.h>
#include <math.h>

// Problem constants
#define KBINS 256
#define Q 4
#define KQ (KBINS * Q)          // 1024 sub-bins
#define BATCH 8
#define NPB (512 * 512)          // 262144 elements per batch
#define NPB4 (NPB / 4)           // 65536 float4 per batch
#define P1_THREADS 256
#define SCALE 4096.0f            // count-encoding scale
#define WLEN 32                  // convolution window taps, jj in [-14, 17]
#define JJ_LO (-14)

// SM-role split: grid = 592 = 4 waves x 148 SMs. bid%148 < 84 -> ATOMS role
// (per-SM smem port), else REDG role (chip L2 atomic ALU pool, ~46 f32/cyc).
// The two resources are disjoint across SMs, so the roles run concurrently.
#define NSM 148
#define ROLE_A_SMS 84
#define CTAS_A_PER_BATCH 42      // 4*84/8
#define CTAS_B_PER_BATCH 32      // 4*64/8
#define CTAS_PER_BATCH 74
#define PART_A 33432             // float4s per batch via ATOMS (51%); 42*796
#define STEP_A (PART_A / CTAS_A_PER_BATCH)   // 796
#define PART_B (NPB4 - PART_A)   // 32104 float4s via REDG

#define PAD4(m) ((m) + ((m) >> 2))   // stride-4 conflict-free padding
#define KQ_PAD (KQ + (KQ >> 2))      // 1280

// Path A target: contiguous per-batch histogram (v4-flushed from shared).
__device__ float g_histA[BATCH * KQ];
// Path B target: 128B-strided -> bin bits hit L2 hash bits {8,10..16},
// spreading the REDG stream over all LTS slices. 1 MB footprint.
#define HSTRIDE 32
__device__ float g_histB[BATCH * KQ * HSTRIDE];
__device__ unsigned int g_sync[BATCH];

__device__ __forceinline__ void redg_add(float* addr, float v) {
    asm volatile("red.global.add.f32 [%0], %1;" :: "l"(addr), "f"(v) : "memory");
}
__device__ __forceinline__ void red_add_v4(float* addr, float4 v) {
    asm volatile("red.global.add.v4.f32 [%0], {%1,%2,%3,%4};"
                 :: "l"(addr), "f"(v.x), "f"(v.y), "f"(v.z), "f"(v.w)
                 : "memory");
}

__global__ void __launch_bounds__(P1_THREADS, 8)
hist_fused(const float* __restrict__ x, float* __restrict__ out) {
    __shared__ float pool[2 * KQ_PAD + 2 * WLEN];   // role A phase uses first KQ
    __shared__ bool is_last;
    float* sh = pool;

    const int tid = threadIdx.x;
    const int bid = blockIdx.x;
    const int wave = bid / NSM;
    const int r = bid % NSM;
    const bool roleA = (r < ROLE_A_SMS);

    int b, i_lo, i_hi;
    if (roleA) {
        int rank = wave * ROLE_A_SMS + r;
        b = rank / CTAS_A_PER_BATCH;
        int sub = rank % CTAS_A_PER_BATCH;
        i_lo = sub * STEP_A;
        i_hi = i_lo + STEP_A;
    } else {
        int rank = wave * (NSM - ROLE_A_SMS) + (r - ROLE_A_SMS);
        b = rank / CTAS_B_PER_BATCH;
        int sub = rank % CTAS_B_PER_BATCH;
        i_lo = PART_A + (sub * PART_B) / CTAS_B_PER_BATCH;
        i_hi = PART_A + ((sub + 1) * PART_B) / CTAS_B_PER_BATCH;
    }

    const float4* __restrict__ xp = reinterpret_cast<const float4*>(x) + (size_t)b * NPB4;
    float* __restrict__ ghA = g_histA + (size_t)b * KQ;
    float* __restrict__ ghB = g_histB + (size_t)b * KQ * HSTRIDE;

    if (roleA) {
        // --- ATOMS role: per-CTA shared histogram, one ATOMS per element ---
        ((float4*)sh)[tid] = make_float4(0.f, 0.f, 0.f, 0.f);
        __syncthreads();

        #pragma unroll 2
        for (int i = i_lo + tid; i < i_hi; i += P1_THREADS) {
            float4 v = xp[i];
            float vals[4] = {v.x, v.y, v.z, v.w};
            #pragma unroll
            for (int j = 0; j < 4; j++) {
                float u = vals[j] * (float)KQ;
                int idx = __float2int_rd(u);
                idx = max(0, min(KQ - 1, idx));
                atomicAdd(&sh[idx], u - (float)idx + (SCALE - 0.5f));
            }
        }
        __syncthreads();
        // Flush: one v4 reduction per thread.
        float4 vv = ((const float4*)sh)[tid];
        red_add_v4(&ghA[tid * 4], vv);
    } else {
        // --- REDG role: fire-and-forget straight into strided L2 bins ---
        for (int i = i_lo + tid; i < i_hi; i += P1_THREADS) {
            float4 v = xp[i];
            float vals[4] = {v.x, v.y, v.z, v.w};
            #pragma unroll
            for (int j = 0; j < 4; j++) {
                float u = vals[j] * (float)KQ;
                int idx = __float2int_rd(u);
                idx = max(0, min(KQ - 1, idx));
                redg_add(&ghB[idx * HSTRIDE], u - (float)idx + (SCALE - 0.5f));
            }
        }
    }

    // --- Arrival protocol: last CTA of this batch proceeds to phase B ---
    __threadfence();
    __syncthreads();
    if (tid == 0) {
        unsigned int old = atomicAdd(&g_sync[b], 1u);
        is_last = (old == CTAS_PER_BATCH - 1);
    }
    __syncthreads();
    if (!is_last) return;

    // --- Phase B: decode + convolution (one CTA per batch) ---
    float* s_cnt = pool;                    // [KQ_PAD]
    float* s_rs  = pool + KQ_PAD;           // [KQ_PAD]
    float* s_w0  = pool + 2 * KQ_PAD;       // [WLEN]
    float* s_w1  = s_w0 + WLEN;             // [WLEN]

    #pragma unroll
    for (int m = tid; m < KQ; m += P1_THREADS) {
        float s = __ldcg(&ghA[m]) + __ldcg(&ghB[m * HSTRIDE]);
        float cnt = rintf(s * (1.0f / SCALE));
        float rs  = s - cnt * SCALE;
        s_cnt[PAD4(m)] = cnt;
        s_rs[PAD4(m)]  = rs;
        ghA[m] = 0.0f;                      // reset for next graph replay
        ghB[m * HSTRIDE] = 0.0f;
    }
    if (tid == 0) g_sync[b] = 0u;

    // Window weights. With Q=4: a+ = 0.625*(jj+0.5), a- = 0.625*(jj-3.5)
    if (tid < WLEN) {
        float jj = (float)(tid + JJ_LO);
        float ap = 0.625f * (jj + 0.5f);
        float am = 0.625f * (jj - 3.5f);
        float sp = 1.0f / (1.0f + __expf(-ap));
        float sm = 1.0f / (1.0f + __expf(-am));
        s_w0[tid] = sp - sm;
        s_w1[tid] = (sp * (1.0f - sp) - sm * (1.0f - sm)) * 0.625f;
    }
    __syncthreads();

    // 32-tap convolution per output bin (thread tid = bin k).
    const int base = tid * Q + JJ_LO;
    float acc = 0.0f;
    #pragma unroll
    for (int w = 0; w < WLEN; w++) {
        int m = base + w;
        if (m >= 0 && m < KQ) {
            int mp = PAD4(m);
            acc = fmaf(s_cnt[mp], s_w0[w], acc);
            acc = fmaf(s_rs[mp],  s_w1[w], acc);
        }
    }
    out[b * KBINS + tid] = acc * (1.0f / (float)NPB);
}

extern "C" void kernel_launch(void* const* d_in, const int* in_sizes, int n_in,
                              void* d_out, int out_size) {
    (void)in_sizes; (void)n_in; (void)out_size;
    const float* x = (const float*)d_in[0];
    float* out = (float*)d_out;
    hist_fused<<<4 * NSM, P1_THREADS>>>(x, out);
}

// round 9
// speedup vs baseline: 1.8739x; 1.8739x over previous
#include <cuda_runtime.h>
#include <math.h>

// Problem constants
#define KBINS 256
#define Q 4
#define KQ (KBINS * Q)          // 1024 sub-bins
#define BATCH 8
#define NPB (512 * 512)          // 262144 elements per batch
#define NPB4 (NPB / 4)           // 65536 float4 per batch
#define CTAS_PER_BATCH 74        // 8*74 = 592 = 148*4 -> exactly 4 CTAs/SM
#define P1_THREADS 256
#define SCALE 4096.0f            // count-encoding scale
#define WLEN 32                  // convolution window taps, jj in [-14, 17]
#define JJ_LO (-14)

#define PAD4(m) ((m) + ((m) >> 2))   // stride-4 conflict-free padding
#define KQ_PAD (KQ + (KQ >> 2))      // 1280

// One combined (cnt,rsum) histogram per batch: 8 * 1024 * 4B = 32 KB.
// Zero at module load; the finishing CTA re-zeroes it each launch so the
// kernel is graph-replay deterministic.
__device__ float g_hist[BATCH * KQ];
__device__ unsigned int g_sync[BATCH];

__device__ __forceinline__ void red_add_v4(float* addr, float4 v) {
    asm volatile("red.global.add.v4.f32 [%0], {%1,%2,%3,%4};"
                 :: "l"(addr), "f"(v.x), "f"(v.y), "f"(v.z), "f"(v.w)
                 : "memory");
}

// ---------------------------------------------------------------------------
// Fused kernel — pure shared-ATOMS. Measured across R4-R8: the per-SM smem
// port at ~1.77 cyc/atomic is the hard floor; L2-atomic offload (REDG) is
// strictly worse in any mixture (R5: 3.2 cyc/elem; R6: additive via shared
// LSU FIFO; R8: collapses at low requester count). One ATOMS per element is
// also the algorithmic minimum. This kernel sits at that roofline.
// Phase A (592 CTAs, perfectly balanced): quantize each x into one of 1024
//   sub-bins; ONE shared atomicAdd per element encoding (count, residual):
//   val = SCALE + r, r in [-0.5, 0.5] sub-bin units. Flush the 4KB shared
//   histogram with one red.global.add.v4.f32 per thread.
// Phase B (last CTA per batch): read the 4KB batch histogram from L2,
//   decode (cnt, rsum), 32-tap convolution, write 256 outputs, reset state.
// ---------------------------------------------------------------------------
__global__ void __launch_bounds__(P1_THREADS, 8)
hist_fused(const float* __restrict__ x, float* __restrict__ out) {
    __shared__ float pool[2 * KQ_PAD + 2 * WLEN];   // phase A uses first KQ
    __shared__ bool is_last;
    float* sh = pool;

    const int tid = threadIdx.x;
    const int b = blockIdx.y;
    const int c = blockIdx.x;

    ((float4*)sh)[tid] = make_float4(0.f, 0.f, 0.f, 0.f);
    __syncthreads();

    // --- Phase A: local accumulation over this CTA's balanced range ---
    const float4* __restrict__ xp = reinterpret_cast<const float4*>(x) + (size_t)b * NPB4;
    const int i_lo = (c * NPB4) / CTAS_PER_BATCH;
    const int i_hi = ((c + 1) * NPB4) / CTAS_PER_BATCH;

    #pragma unroll 2
    for (int i = i_lo + tid; i < i_hi; i += P1_THREADS) {
        float4 v = xp[i];
        float vals[4] = {v.x, v.y, v.z, v.w};
        #pragma unroll
        for (int j = 0; j < 4; j++) {
            float u = vals[j] * (float)KQ;        // position in sub-bin units
            int idx = __float2int_rd(u) & (KQ - 1); // floor; mask = OOB insurance
            // one ATOMS per element: count (SCALE) + residual (u - idx - 0.5)
            atomicAdd(&sh[idx], u - (float)idx + (SCALE - 0.5f));
        }
    }
    __syncthreads();

    // Flush: one v4 reduction per thread (1024 bins / 4 / 256 threads).
    float* __restrict__ gh = g_hist + (size_t)b * KQ;
    {
        float4 vv = ((const float4*)sh)[tid];
        red_add_v4(&gh[tid * 4], vv);
    }

    // --- Arrival protocol: last CTA of this batch proceeds to phase B ---
    __threadfence();
    if (tid == 0) {
        unsigned int old = atomicAdd(&g_sync[b], 1u);
        is_last = (old == CTAS_PER_BATCH - 1);
    }
    __syncthreads();
    if (!is_last) return;

    // --- Phase B: decode + convolution (one CTA per batch) ---
    float* s_cnt = pool;                    // [KQ_PAD]
    float* s_rs  = pool + KQ_PAD;           // [KQ_PAD]
    float* s_w0  = pool + 2 * KQ_PAD;       // [WLEN]
    float* s_w1  = s_w0 + WLEN;             // [WLEN]

    #pragma unroll
    for (int m = tid; m < KQ; m += P1_THREADS) {
        float s = __ldcg(&gh[m]);           // L2-coherent read
        float cnt = rintf(s * (1.0f / SCALE));
        float rs  = s - cnt * SCALE;
        s_cnt[PAD4(m)] = cnt;
        s_rs[PAD4(m)]  = rs;
        gh[m] = 0.0f;                       // reset for next graph replay
    }
    if (tid == 0) g_sync[b] = 0u;

    // Window weights (float). With Q=4, Delta = 1/1024:
    //   a+ = 0.625*(jj + 0.5), a- = 0.625*(jj - 3.5)
    //   w0 = sigmoid(a+) - sigmoid(a-);  w1 = 0.625*[sig'(a+) - sig'(a-)]
    if (tid < WLEN) {
        float jj = (float)(tid + JJ_LO);
        float ap = 0.625f * (jj + 0.5f);
        float am = 0.625f * (jj - 3.5f);
        float sp = 1.0f / (1.0f + __expf(-ap));
        float sm = 1.0f / (1.0f + __expf(-am));
        s_w0[tid] = sp - sm;
        s_w1[tid] = (sp * (1.0f - sp) - sm * (1.0f - sm)) * 0.625f;
    }
    __syncthreads();

    // 32-tap convolution per output bin (thread tid = bin k).
    const int base = tid * Q + JJ_LO;
    float acc = 0.0f;
    #pragma unroll
    for (int w = 0; w < WLEN; w++) {
        int m = base + w;
        if (m >= 0 && m < KQ) {
            int mp = PAD4(m);
            acc = fmaf(s_cnt[mp], s_w0[w], acc);
            acc = fmaf(s_rs[mp],  s_w1[w], acc);
        }
    }
    out[b * KBINS + tid] = acc * (1.0f / (float)NPB);
}

extern "C" void kernel_launch(void* const* d_in, const int* in_sizes, int n_in,
                              void* d_out, int out_size) {
    (void)in_sizes; (void)n_in; (void)out_size;
    const float* x = (const float*)d_in[0];
    float* out = (float*)d_out;
    dim3 grid(CTAS_PER_BATCH, BATCH);
    hist_fused<<<grid, P1_THREADS>>>(x, out);
}

// round 10
// speedup vs baseline: 1.9250x; 1.0273x over previous
#include <cuda_runtime.h>
#include <math.h>

// Problem constants
#define KBINS 256
#define Q 4
#define KQ (KBINS * Q)          // 1024 sub-bins
#define BATCH 8
#define NPB (512 * 512)          // 262144 elements per batch
#define NPB4 (NPB / 4)           // 65536 float4 per batch
#define CTAS_PER_BATCH 74        // 8*74 = 592 = 148*4 -> exactly 4 CTAs/SM
#define P1_THREADS 256
#define SCALE 4096.0f            // count-encoding scale
#define WLEN 32                  // convolution window taps, jj in [-14, 17]
#define JJ_LO (-14)

#define PAD4(m) ((m) + ((m) >> 2))   // stride-4 conflict-free padding
#define KQ_PAD (KQ + (KQ >> 2))      // 1280

// One combined (cnt,rsum) histogram per batch: 8 * 1024 * 4B = 32 KB.
// Zero at module load; the finishing CTA re-zeroes it each launch so the
// kernel is graph-replay deterministic.
__device__ float g_hist[BATCH * KQ];
__device__ unsigned int g_sync[BATCH];

__device__ __forceinline__ void red_add_v4(float* addr, float4 v) {
    asm volatile("red.global.add.v4.f32 [%0], {%1,%2,%3,%4};"
                 :: "l"(addr), "f"(v.x), "f"(v.y), "f"(v.z), "f"(v.w)
                 : "memory");
}

// ---------------------------------------------------------------------------
// Fused kernel — pure shared-ATOMS. Established across R4-R9: the per-SM
// smem-atomic port at ~1.77 cyc/atomic is the hard floor for this problem;
// one ATOMS per element is the algorithmic minimum; every L2-atomic offload
// mixture measured strictly worse (R5: 3.2 cyc/elem; R6: additive via the
// shared per-SM L1tex FIFO; R8: REDG throughput collapses at low requester
// count). This kernel sits at that roofline — champion configuration (R7).
//
// Phase A (592 CTAs, perfectly balanced, 4/SM): quantize each x into one of
//   1024 sub-bins; ONE shared atomicAdd per element encoding (count,
//   residual): val = SCALE + r, r in [-0.5, 0.5] sub-bin units. Flush the
//   4KB shared histogram with one red.global.add.v4.f32 per thread.
// Phase B (last CTA per batch): read the 4KB batch histogram from L2,
//   decode (cnt, rsum), 32-tap first-order-corrected convolution, write
//   256 outputs, reset state for graph replay.
// ---------------------------------------------------------------------------
__global__ void __launch_bounds__(P1_THREADS, 8)
hist_fused(const float* __restrict__ x, float* __restrict__ out) {
    __shared__ float pool[2 * KQ_PAD + 2 * WLEN];   // phase A uses first KQ
    __shared__ bool is_last;
    float* sh = pool;

    const int tid = threadIdx.x;
    const int b = blockIdx.y;
    const int c = blockIdx.x;

    ((float4*)sh)[tid] = make_float4(0.f, 0.f, 0.f, 0.f);
    __syncthreads();

    // --- Phase A: local accumulation over this CTA's balanced range ---
    const float4* __restrict__ xp = reinterpret_cast<const float4*>(x) + (size_t)b * NPB4;
    const int i_lo = (c * NPB4) / CTAS_PER_BATCH;
    const int i_hi = ((c + 1) * NPB4) / CTAS_PER_BATCH;

    #pragma unroll 2
    for (int i = i_lo + tid; i < i_hi; i += P1_THREADS) {
        float4 v = xp[i];
        float vals[4] = {v.x, v.y, v.z, v.w};
        #pragma unroll
        for (int j = 0; j < 4; j++) {
            float u = vals[j] * (float)KQ;        // position in sub-bin units
            int idx = __float2int_rd(u);          // floor as direct F2I.FLOOR
            idx = max(0, min(KQ - 1, idx));
            // one ATOMS per element: count (SCALE) + residual (u - idx - 0.5)
            atomicAdd(&sh[idx], u - (float)idx + (SCALE - 0.5f));
        }
    }
    __syncthreads();

    // Flush: one v4 reduction per thread (1024 bins / 4 / 256 threads).
    float* __restrict__ gh = g_hist + (size_t)b * KQ;
    {
        float4 vv = ((const float4*)sh)[tid];
        red_add_v4(&gh[tid * 4], vv);
    }

    // --- Arrival protocol: last CTA of this batch proceeds to phase B ---
    __threadfence();
    if (tid == 0) {
        unsigned int old = atomicAdd(&g_sync[b], 1u);
        is_last = (old == CTAS_PER_BATCH - 1);
    }
    __syncthreads();
    if (!is_last) return;

    // --- Phase B: decode + convolution (one CTA per batch) ---
    float* s_cnt = pool;                    // [KQ_PAD]
    float* s_rs  = pool + KQ_PAD;           // [KQ_PAD]
    float* s_w0  = pool + 2 * KQ_PAD;       // [WLEN]
    float* s_w1  = s_w0 + WLEN;             // [WLEN]

    #pragma unroll
    for (int m = tid; m < KQ; m += P1_THREADS) {
        float s = __ldcg(&gh[m]);           // L2-coherent read
        float cnt = rintf(s * (1.0f / SCALE));
        float rs  = s - cnt * SCALE;
        s_cnt[PAD4(m)] = cnt;
        s_rs[PAD4(m)]  = rs;
        gh[m] = 0.0f;                       // reset for next graph replay
    }
    if (tid == 0) g_sync[b] = 0u;

    // Window weights (float). With Q=4, Delta = 1/1024:
    //   a+ = 0.625*(jj + 0.5), a- = 0.625*(jj - 3.5)
    //   w0 = sigmoid(a+) - sigmoid(a-);  w1 = 0.625*[sig'(a+) - sig'(a-)]
    if (tid < WLEN) {
        float jj = (float)(tid + JJ_LO);
        float ap = 0.625f * (jj + 0.5f);
        float am = 0.625f * (jj - 3.5f);
        float sp = 1.0f / (1.0f + __expf(-ap));
        float sm = 1.0f / (1.0f + __expf(-am));
        s_w0[tid] = sp - sm;
        s_w1[tid] = (sp * (1.0f - sp) - sm * (1.0f - sm)) * 0.625f;
    }
    __syncthreads();

    // 32-tap convolution per output bin (thread tid = bin k).
    const int base = tid * Q + JJ_LO;
    float acc = 0.0f;
    #pragma unroll
    for (int w = 0; w < WLEN; w++) {
        int m = base + w;
        if (m >= 0 && m < KQ) {
            int mp = PAD4(m);
            acc = fmaf(s_cnt[mp], s_w0[w], acc);
            acc = fmaf(s_rs[mp],  s_w1[w], acc);
        }
    }
    out[b * KBINS + tid] = acc * (1.0f / (float)NPB);
}

extern "C" void kernel_launch(void* const* d_in, const int* in_sizes, int n_in,
                              void* d_out, int out_size) {
    (void)in_sizes; (void)n_in; (void)out_size;
    const float* x = (const float*)d_in[0];
    float* out = (float*)d_out;
    dim3 grid(CTAS_PER_BATCH, BATCH);
    hist_fused<<<grid, P1_THREADS>>>(x, out);
}

// round 11
// speedup vs baseline: 2.1175x; 1.1000x over previous
#include <cuda_runtime.h>
#include <math.h>

// Problem constants
#define KBINS 256
#define Q 4
#define KQ (KBINS * Q)          // 1024 sub-bins
#define BATCH 8
#define NPB (512 * 512)          // 262144 elements per batch
#define NPB4 (NPB / 4)           // 65536 float4 per batch
#define CTAS_PER_BATCH 148       // 8*148 = 1184 = 148*8 -> exactly 8 CTAs/SM
#define P1_THREADS 256
#define SCALE 4096.0f            // count-encoding scale
#define WLEN 32                  // convolution window taps, jj in [-14, 17]
#define JJ_LO (-14)

#define PAD4(m) ((m) + ((m) >> 2))   // stride-4 conflict-free padding
#define KQ_PAD (KQ + (KQ >> 2))      // 1280

// One combined (cnt,rsum) histogram per batch: 8 * 1024 * 4B = 32 KB.
// Zero at module load; the finishing CTA re-zeroes it each launch so the
// kernel is graph-replay deterministic.
__device__ float g_hist[BATCH * KQ];
__device__ unsigned int g_sync[BATCH];

__device__ __forceinline__ void red_add_v4(float* addr, float4 v) {
    asm volatile("red.global.add.v4.f32 [%0], {%1,%2,%3,%4};"
                 :: "l"(addr), "f"(v.x), "f"(v.y), "f"(v.z), "f"(v.w)
                 : "memory");
}

// ---------------------------------------------------------------------------
// Fused kernel — pure shared-ATOMS at the measured smem-atomic-port floor
// (~1.77 cyc/atomic, R4-R10). One ATOMS per element is the algorithmic
// minimum; all L2-atomic offload mixtures measured strictly worse (R5, R6,
// R8). This round's only change vs the R7 champion: 8 CTAs/SM instead of 4
// (grid 1184) to deepen the warp pool over LDG reload bubbles and shrink
// the pre-phase-B finish skew.
//
// Phase A (1184 CTAs, perfectly balanced, 8/SM): quantize each x into one
//   of 1024 sub-bins; ONE shared atomicAdd per element encoding (count,
//   residual): val = SCALE + r, r in [-0.5, 0.5] sub-bin units. Flush the
//   4KB shared histogram with one red.global.add.v4.f32 per thread.
// Phase B (last CTA per batch): read the 4KB batch histogram from L2,
//   decode (cnt, rsum), 32-tap first-order-corrected convolution, write
//   256 outputs, reset state for graph replay.
// ---------------------------------------------------------------------------
__global__ void __launch_bounds__(P1_THREADS, 8)
hist_fused(const float* __restrict__ x, float* __restrict__ out) {
    __shared__ float pool[2 * KQ_PAD + 2 * WLEN];   // phase A uses first KQ
    __shared__ bool is_last;
    float* sh = pool;

    const int tid = threadIdx.x;
    const int b = blockIdx.y;
    const int c = blockIdx.x;

    ((float4*)sh)[tid] = make_float4(0.f, 0.f, 0.f, 0.f);
    __syncthreads();

    // --- Phase A: local accumulation over this CTA's balanced range ---
    const float4* __restrict__ xp = reinterpret_cast<const float4*>(x) + (size_t)b * NPB4;
    const int i_lo = (c * NPB4) / CTAS_PER_BATCH;
    const int i_hi = ((c + 1) * NPB4) / CTAS_PER_BATCH;

    #pragma unroll 2
    for (int i = i_lo + tid; i < i_hi; i += P1_THREADS) {
        float4 v = xp[i];
        float vals[4] = {v.x, v.y, v.z, v.w};
        #pragma unroll
        for (int j = 0; j < 4; j++) {
            float u = vals[j] * (float)KQ;        // position in sub-bin units
            int idx = __float2int_rd(u);          // floor as direct F2I.FLOOR
            idx = max(0, min(KQ - 1, idx));
            // one ATOMS per element: count (SCALE) + residual (u - idx - 0.5)
            atomicAdd(&sh[idx], u - (float)idx + (SCALE - 0.5f));
        }
    }
    __syncthreads();

    // Flush: one v4 reduction per thread (1024 bins / 4 / 256 threads).
    float* __restrict__ gh = g_hist + (size_t)b * KQ;
    {
        float4 vv = ((const float4*)sh)[tid];
        red_add_v4(&gh[tid * 4], vv);
    }

    // --- Arrival protocol: last CTA of this batch proceeds to phase B ---
    __threadfence();
    if (tid == 0) {
        unsigned int old = atomicAdd(&g_sync[b], 1u);
        is_last = (old == CTAS_PER_BATCH - 1);
    }
    __syncthreads();
    if (!is_last) return;

    // --- Phase B: decode + convolution (one CTA per batch) ---
    float* s_cnt = pool;                    // [KQ_PAD]
    float* s_rs  = pool + KQ_PAD;           // [KQ_PAD]
    float* s_w0  = pool + 2 * KQ_PAD;       // [WLEN]
    float* s_w1  = s_w0 + WLEN;             // [WLEN]

    #pragma unroll
    for (int m = tid; m < KQ; m += P1_THREADS) {
        float s = __ldcg(&gh[m]);           // L2-coherent read
        float cnt = rintf(s * (1.0f / SCALE));
        float rs  = s - cnt * SCALE;
        s_cnt[PAD4(m)] = cnt;
        s_rs[PAD4(m)]  = rs;
        gh[m] = 0.0f;                       // reset for next graph replay
    }
    if (tid == 0) g_sync[b] = 0u;

    // Window weights (float). With Q=4, Delta = 1/1024:
    //   a+ = 0.625*(jj + 0.5), a- = 0.625*(jj - 3.5)
    //   w0 = sigmoid(a+) - sigmoid(a-);  w1 = 0.625*[sig'(a+) - sig'(a-)]
    if (tid < WLEN) {
        float jj = (float)(tid + JJ_LO);
        float ap = 0.625f * (jj + 0.5f);
        float am = 0.625f * (jj - 3.5f);
        float sp = 1.0f / (1.0f + __expf(-ap));
        float sm = 1.0f / (1.0f + __expf(-am));
        s_w0[tid] = sp - sm;
        s_w1[tid] = (sp * (1.0f - sp) - sm * (1.0f - sm)) * 0.625f;
    }
    __syncthreads();

    // 32-tap convolution per output bin (thread tid = bin k).
    const int base = tid * Q + JJ_LO;
    float acc = 0.0f;
    #pragma unroll
    for (int w = 0; w < WLEN; w++) {
        int m = base + w;
        if (m >= 0 && m < KQ) {
            int mp = PAD4(m);
            acc = fmaf(s_cnt[mp], s_w0[w], acc);
            acc = fmaf(s_rs[mp],  s_w1[w], acc);
        }
    }
    out[b * KBINS + tid] = acc * (1.0f / (float)NPB);
}

extern "C" void kernel_launch(void* const* d_in, const int* in_sizes, int n_in,
                              void* d_out, int out_size) {
    (void)in_sizes; (void)n_in; (void)out_size;
    const float* x = (const float*)d_in[0];
    float* out = (float*)d_out;
    dim3 grid(CTAS_PER_BATCH, BATCH);
    hist_fused<<<grid, P1_THREADS>>>(x, out);
}